// round 7
// baseline (speedup 1.0000x reference)
#include <cuda_runtime.h>
#include <cuda_fp16.h>
#include <cstdint>

#define DDIM 512
#define KDIM 512
#define BM   64
#define BK   16
#define NTH  256
#define NCH  32

// static scratch (no allocations allowed)
__device__ __half g_cb[KDIM * DDIM];   // clusters fp16 [K][D]
__device__ float g_c2[KDIM];

// ---- smem layout (bytes) ----
#define BSTAGEB 16384u                // 512 rows * 32B, XOR-swizzled, no padding
#define OFF_A   0u                    // 64 rows * 1024B (swizzled) = 65536, resident
#define OFF_B   65536u                // 2 * 16384 -> 98304
#define OFF_C2  98304u                // 512*4  -> 100352
#define OFF_X2  100352u               // 64*4   -> 100608
#define OFF_RS  100608u               // 4*64*4 -> 101632
#define SMEM_TOTAL 101632u            // 99.25 KB -> 2 CTAs/SM

// ---------------- helpers ----------------
__device__ __forceinline__ float frcp(float a) {
    float r; asm("rcp.approx.ftz.f32 %0, %1;" : "=f"(r) : "f"(a)); return r;
}
__device__ __forceinline__ uint32_t pkh(float a, float b) {
    __half2 h = __floats2half2_rn(a, b);
    return *reinterpret_cast<uint32_t*>(&h);
}
// A swizzle: row r (0..63) x byte-col cb (0..1023); XOR bits[4:6] with row%8
__device__ __forceinline__ uint32_t asw(uint32_t r, uint32_t cb) {
    return r * 1024u + (cb ^ ((r & 7u) << 4));
}
__device__ __forceinline__ void cp16(uint32_t dst, const void* src) {
    asm volatile("cp.async.cg.shared.global [%0], [%1], 16;"
                 :: "r"(dst), "l"(__cvta_generic_to_global(src)) : "memory");
}
#define CP_COMMIT() asm volatile("cp.async.commit_group;" ::: "memory")
template <int N>
__device__ __forceinline__ void cp_wait() {
    asm volatile("cp.async.wait_group %0;" :: "n"(N) : "memory");
}
__device__ __forceinline__ void ldsm4(uint32_t* r, uint32_t a) {
    asm volatile("ldmatrix.sync.aligned.m8n8.x4.shared.b16 {%0,%1,%2,%3}, [%4];"
                 : "=r"(r[0]), "=r"(r[1]), "=r"(r[2]), "=r"(r[3]) : "r"(a));
}
// fp16-accumulator HMMA
__device__ __forceinline__ void mma_f16(uint32_t* c, const uint32_t* a, uint32_t b0, uint32_t b1) {
    asm volatile("mma.sync.aligned.m16n8k16.row.col.f16.f16.f16.f16 "
                 "{%0,%1}, {%2,%3,%4,%5}, {%6,%7}, {%0,%1};"
                 : "+r"(c[0]), "+r"(c[1])
                 : "r"(a[0]), "r"(a[1]), "r"(a[2]), "r"(a[3]), "r"(b0), "r"(b1));
}

// ---------------- prep: clusters -> fp16, c2 fp32 ----------------
__global__ void prep_kernel(const float* __restrict__ clusters) {
    int k = blockIdx.x, tid = threadIdx.x;
    const float* row = clusters + (size_t)k * DDIM;
    float s = 0.f;
    for (int d = tid; d < DDIM; d += 128) {
        float v = row[d];
        s += v * v;
        g_cb[(size_t)k * DDIM + d] = __float2half(v);
    }
    #pragma unroll
    for (int o = 16; o > 0; o >>= 1) s += __shfl_xor_sync(0xffffffffu, s, o);
    __shared__ float red[4];
    if ((tid & 31) == 0) red[tid >> 5] = s;
    __syncthreads();
    if (tid == 0) g_c2[k] = red[0] + red[1] + red[2] + red[3];
}

// ---------------- main fused kernel ----------------
// CTA: 64 rows x all 512 cols. 256 threads, 2 CTAs/SM. Warp grid 2(M) x 4(N),
// warp tile 32x128, fp16 accumulators. A resident in smem; B streamed BK=16, 2-stage.
__global__ void __launch_bounds__(NTH, 2)
cluster_kernel(const float* __restrict__ x, float* __restrict__ out) {
    extern __shared__ char smem[];
    char*  smA = smem + OFF_A;
    float* c2s = (float*)(smem + OFF_C2);
    float* x2s = (float*)(smem + OFF_X2);
    float* rss = (float*)(smem + OFF_RS);

    const int tid = threadIdx.x, lane = tid & 31, wid = tid >> 5;
    const int wm = wid & 1, wn = wid >> 1;          // 2 x 4 warp grid
    const long row0 = (long)blockIdx.x * BM;
    const float* xblk = x + row0 * DDIM;

    const uint32_t sA = (uint32_t)__cvta_generic_to_shared(smA);
    const uint32_t sB = (uint32_t)__cvta_generic_to_shared(smem + OFF_B);

    // B loader: chunk c = k-cols [c*16, c*16+16) of all 512 cluster rows (16 KB)
    // smem layout: row*32 + (seg16 ^ ((row&4)<<2))  -- conflict-free XOR swizzle
    auto loadB = [&](int c, int s) {
        #pragma unroll
        for (int i = 0; i < 4; i++) {
            int idx = tid + i * NTH;                // 0..1023
            int brow = idx >> 1, seg = (idx & 1) << 4;
            uint32_t dst = sB + s * BSTAGEB + brow * 32 + (seg ^ ((brow & 4) << 2));
            const char* src = (const char*)g_cb + (size_t)brow * (DDIM * 2) + c * (BK * 2) + seg;
            cp16(dst, src);
        }
        CP_COMMIT();
    };

    loadB(0, 0);   // prefetch chunk 0 while we convert A

    for (int i = tid; i < KDIM; i += NTH) c2s[i] = g_c2[i];

    // ---- A: convert x tile fp32 -> fp16 into swizzled resident smem, + ||x||^2 ----
    {
        const int arow = tid >> 2, aq = tid & 3;    // 4 threads per row, 128 floats each
        const float* src = xblk + (size_t)arow * DDIM;
        float x2a = 0.f;
        #pragma unroll
        for (int j = 0; j < 16; j++) {
            const int fc = aq * 8 + j * 32;         // float col
            float4 u = *(const float4*)(src + fc);
            float4 v = *(const float4*)(src + fc + 4);
            x2a += u.x * u.x + u.y * u.y + u.z * u.z + u.w * u.w;
            x2a += v.x * v.x + v.y * v.y + v.z * v.z + v.w * v.w;
            uint4 w = make_uint4(pkh(u.x, u.y), pkh(u.z, u.w), pkh(v.x, v.y), pkh(v.z, v.w));
            *(uint4*)(smA + asw(arow, fc * 2)) = w;
        }
        x2a += __shfl_xor_sync(0xffffffffu, x2a, 1);
        x2a += __shfl_xor_sync(0xffffffffu, x2a, 2);
        if ((lane & 3) == 0) x2s[arow] = x2a;
    }

    uint32_t acc[2][16][2];
    #pragma unroll
    for (int mt = 0; mt < 2; mt++)
        #pragma unroll
        for (int nt = 0; nt < 16; nt++) { acc[mt][nt][0] = 0u; acc[mt][nt][1] = 0u; }

    const uint32_t lmr = lane & 15, lmc = (lane >> 4) * 16;
    const uint32_t xr  = (lmr & 7u) << 4;                       // A swizzle term
    const uint32_t aro0 = (uint32_t)(wm * 32 + lmr) * 1024u;
    const uint32_t aro1 = (uint32_t)(wm * 32 + 16 + lmr) * 1024u;
    // B ldsm base within a stage: row = wn*128 + lmr (bt*512 folds into immediate)
    const uint32_t bro = (uint32_t)(wn * 128 + lmr) * 32u + (lmc ^ ((lmr & 4u) << 2));

    // ---- mainloop: 32 K-chunks (k16 each), A resident, B double-buffered ----
    #pragma unroll 1
    for (int c = 0; c < NCH; c++) {
        cp_wait<0>();
        __syncthreads();                       // chunk c visible; other stage free
        if (c + 1 < NCH) loadB(c + 1, (c + 1) & 1);

        const uint32_t acb = ((uint32_t)(c * 32) + lmc) ^ xr;
        uint32_t a0[4], a1[4];
        ldsm4(a0, sA + aro0 + acb);
        ldsm4(a1, sA + aro1 + acb);
        const uint32_t bbase = sB + (c & 1) * BSTAGEB + bro;
        #pragma unroll
        for (int bt = 0; bt < 8; bt++) {
            uint32_t b[4];
            ldsm4(b, bbase + bt * 512);
            mma_f16(acc[0][2 * bt + 0], a0, b[0], b[2]);
            mma_f16(acc[0][2 * bt + 1], a0, b[1], b[3]);
            mma_f16(acc[1][2 * bt + 0], a1, b[0], b[2]);
            mma_f16(acc[1][2 * bt + 1], a1, b[1], b[3]);
        }
    }

    // ---- epilogue pass 1: row sums ----
    #pragma unroll
    for (int mt = 0; mt < 2; mt++) {
        #pragma unroll
        for (int rr = 0; rr < 2; rr++) {
            const int row = wm * 32 + mt * 16 + (lane >> 2) + rr * 8;
            const float x2v = x2s[row];
            float rsum = 0.f;
            #pragma unroll
            for (int nt = 0; nt < 16; nt++) {
                float2 f = __half22float2(*(__half2*)&acc[mt][nt][rr]);
                const int col = wn * 128 + nt * 8 + (lane & 3) * 2;
                float d0 = fmaxf(fmaf(-2.f, f.x, x2v + c2s[col]), 0.f);
                float d1 = fmaxf(fmaf(-2.f, f.y, x2v + c2s[col + 1]), 0.f);
                rsum += frcp(1.f + d0) + frcp(1.f + d1);
            }
            rsum += __shfl_xor_sync(0xffffffffu, rsum, 1);
            rsum += __shfl_xor_sync(0xffffffffu, rsum, 2);
            if ((lane & 3) == 0) rss[wn * 64 + row] = rsum;
        }
    }
    __syncthreads();

    // ---- epilogue pass 2: normalize (recompute q in fp32) and store ----
    #pragma unroll
    for (int mt = 0; mt < 2; mt++) {
        #pragma unroll
        for (int rr = 0; rr < 2; rr++) {
            const int row = wm * 32 + mt * 16 + (lane >> 2) + rr * 8;
            const float x2v = x2s[row];
            const float inv = frcp(rss[row] + rss[64 + row] + rss[128 + row] + rss[192 + row]);
            float* orow = out + (row0 + row) * KDIM;
            #pragma unroll
            for (int nt = 0; nt < 16; nt++) {
                float2 f = __half22float2(*(__half2*)&acc[mt][nt][rr]);
                const int col = wn * 128 + nt * 8 + (lane & 3) * 2;
                float d0 = fmaxf(fmaf(-2.f, f.x, x2v + c2s[col]), 0.f);
                float d1 = fmaxf(fmaf(-2.f, f.y, x2v + c2s[col + 1]), 0.f);
                *(float2*)&orow[col] = make_float2(frcp(1.f + d0) * inv, frcp(1.f + d1) * inv);
            }
        }
    }
}

extern "C" void kernel_launch(void* const* d_in, const int* in_sizes, int n_in,
                              void* d_out, int out_size) {
    const float* x        = (const float*)d_in[0];
    const float* clusters = (const float*)d_in[1];
    float* out = (float*)d_out;
    int n = in_sizes[0] / DDIM;   // 131072

    cudaFuncSetAttribute(cluster_kernel, cudaFuncAttributeMaxDynamicSharedMemorySize, SMEM_TOTAL);
    prep_kernel<<<KDIM, 128>>>(clusters);
    cluster_kernel<<<n / BM, NTH, SMEM_TOTAL>>>(x, out);
}